// round 4
// baseline (speedup 1.0000x reference)
#include <cuda_runtime.h>

#define B_   2
#define SQ_  2048
#define SK_  2048
#define D_   1024
#define H_   16
#define HD_  64

typedef unsigned long long ull;

// Scratch (allocation-free rule: __device__ globals)
__device__ float g_q[B_*H_*SQ_*HD_];     // [B,H,SQ,HD]
__device__ float g_k[B_*H_*SK_*HD_];     // [B,H,SK,HD]
__device__ float g_v[B_*H_*SK_*HD_];     // [B,H,SK,HD]
__device__ float g_attn[B_*SQ_*D_];      // [B,SQ,D]

// ---------------- packed f32x2 helpers (FFMA2 path) ----------------
__device__ __forceinline__ ull pack2(float x) {
    ull r;
    asm("mov.b64 %0, {%1, %1};" : "=l"(r) : "f"(x));
    return r;
}
__device__ __forceinline__ void ffma2(ull& d, ull a, ull b) {
    asm("fma.rn.f32x2 %0, %1, %2, %0;" : "+l"(d) : "l"(a), "l"(b));
}
__device__ __forceinline__ void mul2(ull& d, ull a) {
    asm("mul.rn.f32x2 %0, %0, %1;" : "+l"(d) : "l"(a));
}
__device__ __forceinline__ float2 unpack2(ull v) {
    float2 r;
    asm("mov.b64 {%0, %1}, %2;" : "=f"(r.x), "=f"(r.y) : "l"(v));
    return r;
}

// ----------------------------------------------------------------------------
// SGEMM (FFMA2): C[M,N] = A[M,K] @ B'[K,N] + bias[N]
// BMODE 0: Bm row-major [K,N].
// BMODE 1: Bm per-head [H, K, 64]; col n -> (h=n>>6, e=n&63).
// OMODE 0: C row-major [M,N].  OMODE 1: C as [B,H,S,64].
// Tile 128x128x8, 256 threads, 8x8 per thread, register prefetch.
// ----------------------------------------------------------------------------
template<int BMODE, int OMODE>
__global__ __launch_bounds__(256) void sgemm(
    const float* __restrict__ A, const float* __restrict__ Bm,
    const float* __restrict__ bias, float* __restrict__ C,
    int M, int N, int K, int S)
{
    const int BK = 8;
    __shared__ float As[BK][128];
    __shared__ float Bs[BK][128];

    int tid = threadIdx.x;
    int tx = tid & 15, ty = tid >> 4;
    int row0 = blockIdx.y * 128, col0 = blockIdx.x * 128;

    int arow = tid >> 1, acol = (tid & 1) * 4;
    int brow = tid >> 5, bcol = (tid & 31) * 4;

    ull acc2[8][4];
#pragma unroll
    for (int i = 0; i < 8; i++)
#pragma unroll
        for (int j = 0; j < 4; j++) acc2[i][j] = 0ull;

    const float* Aptr = A + (long long)(row0 + arow) * K + acol;

    auto loadB = [&](int k0) -> float4 {
        if (BMODE == 0) {
            return *(const float4*)&Bm[(long long)(k0 + brow) * N + col0 + bcol];
        } else {
            int n = col0 + bcol;
            int h = n >> 6, e = n & 63;
            return *(const float4*)&Bm[((long long)h * K + (k0 + brow)) * HD_ + e];
        }
    };

    float4 av = *(const float4*)(Aptr);
    float4 bv = loadB(0);

    for (int k0 = 0; k0 < K; k0 += BK) {
        As[acol + 0][arow] = av.x;
        As[acol + 1][arow] = av.y;
        As[acol + 2][arow] = av.z;
        As[acol + 3][arow] = av.w;
        *(float4*)&Bs[brow][bcol] = bv;
        __syncthreads();

        if (k0 + BK < K) {
            av = *(const float4*)(Aptr + k0 + BK);
            bv = loadB(k0 + BK);
        }

#pragma unroll
        for (int kk = 0; kk < BK; kk++) {
            float4 a0 = *(const float4*)&As[kk][ty * 8];
            float4 a1 = *(const float4*)&As[kk][ty * 8 + 4];
            ulonglong2 b0 = *(const ulonglong2*)&Bs[kk][tx * 8];
            ulonglong2 b1 = *(const ulonglong2*)&Bs[kk][tx * 8 + 4];
            float ar[8] = {a0.x, a0.y, a0.z, a0.w, a1.x, a1.y, a1.z, a1.w};
#pragma unroll
            for (int i = 0; i < 8; i++) {
                ull aa = pack2(ar[i]);
                ffma2(acc2[i][0], aa, b0.x);
                ffma2(acc2[i][1], aa, b0.y);
                ffma2(acc2[i][2], aa, b1.x);
                ffma2(acc2[i][3], aa, b1.y);
            }
        }
        __syncthreads();
    }

    // Epilogue: bias + store
#pragma unroll
    for (int i = 0; i < 8; i++) {
        int row = row0 + ty * 8 + i;
#pragma unroll
        for (int j4 = 0; j4 < 2; j4++) {
            int col = col0 + tx * 8 + j4 * 4;
            float2 e0 = unpack2(acc2[i][j4 * 2 + 0]);
            float2 e1 = unpack2(acc2[i][j4 * 2 + 1]);
            float4 o;
            o.x = e0.x + bias[col + 0];
            o.y = e0.y + bias[col + 1];
            o.z = e1.x + bias[col + 2];
            o.w = e1.y + bias[col + 3];
            long long idx;
            if (OMODE == 0) {
                idx = (long long)row * N + col;
            } else {
                int b = row / S, s = row - b * S;
                int h = col >> 6, e = col & 63;
                idx = (((long long)(b * H_ + h) * S) + s) * HD_ + e;
            }
            *(float4*)&C[idx] = o;
        }
    }
}

// ----------------------------------------------------------------------------
// Flash attention (fp32 via FFMA2): block = 128 q rows of one (b,h),
// key tiles of 128. 256 threads (16x16): S-tile 8q x 8k, PV-tile 8q x 4d.
// smem: Qst[64][132] + Kst[64][132] + Vs[128][68] + Ps[128][132] = 169984 B
// ----------------------------------------------------------------------------
__global__ __launch_bounds__(256) void flash2(
    const float* __restrict__ Q, const float* __restrict__ Kg,
    const float* __restrict__ Vg, float* __restrict__ Og)
{
    extern __shared__ float sm[];
    float (*Qst)[132] = (float(*)[132])(sm);                       // [d][q]
    float (*Kst)[132] = (float(*)[132])(sm + 64 * 132);            // [d][k]
    float (*Vs)[68]   = (float(*)[68]) (sm + 2 * 64 * 132);        // [k][d]
    float (*Ps)[132]  = (float(*)[132])(sm + 2 * 64 * 132 + 128 * 68); // [q][k]

    int tid = threadIdx.x;
    int tx = tid & 15, ty = tid >> 4;
    int bh = blockIdx.y;
    int qbase = blockIdx.x * 128;

    const float* Qp = Q + ((long long)bh * SQ_ + qbase) * HD_;
    const float* Kp = Kg + (long long)bh * SK_ * HD_;
    const float* Vp = Vg + (long long)bh * SK_ * HD_;

    // Load Q transposed [d][q], pre-scaled by 1/sqrt(HD)
    for (int i = tid; i < 128 * 64; i += 256) {
        int r = i >> 6, d = i & 63;
        Qst[d][r] = Qp[(long long)r * HD_ + d] * 0.125f;
    }

    ull acc_o[8][2];
    float m_i[8], l_i[8];
#pragma unroll
    for (int i = 0; i < 8; i++) {
        acc_o[i][0] = 0ull; acc_o[i][1] = 0ull;
        m_i[i] = -1e30f; l_i[i] = 0.f;
    }

    for (int kt = 0; kt < SK_; kt += 128) {
        __syncthreads();   // previous PV readers done
        for (int i = tid; i < 128 * 64; i += 256) {
            int r = i >> 6, d = i & 63;
            float kvx = Kp[(long long)(kt + r) * HD_ + d];
            float vvx = Vp[(long long)(kt + r) * HD_ + d];
            Kst[d][r] = kvx;
            Vs[r][d]  = vvx;
        }
        __syncthreads();

        // ---- S = Q @ K^T (8q x 8k per thread, FFMA2 over key pairs) ----
        ull s2[8][4];
#pragma unroll
        for (int i = 0; i < 8; i++)
#pragma unroll
            for (int j = 0; j < 4; j++) s2[i][j] = 0ull;

#pragma unroll 4
        for (int d = 0; d < 64; d++) {
            ulonglong2 ka = *(const ulonglong2*)&Kst[d][tx * 8];
            ulonglong2 kb = *(const ulonglong2*)&Kst[d][tx * 8 + 4];
            float4 qa = *(const float4*)&Qst[d][ty * 8];
            float4 qb = *(const float4*)&Qst[d][ty * 8 + 4];
            float qs[8] = {qa.x, qa.y, qa.z, qa.w, qb.x, qb.y, qb.z, qb.w};
#pragma unroll
            for (int i = 0; i < 8; i++) {
                ull qq = pack2(qs[i]);
                ffma2(s2[i][0], qq, ka.x);
                ffma2(s2[i][1], qq, ka.y);
                ffma2(s2[i][2], qq, kb.x);
                ffma2(s2[i][3], qq, kb.y);
            }
        }

        // ---- online softmax per q row (row = 16 tx lanes in half-warp) ----
#pragma unroll
        for (int i = 0; i < 8; i++) {
            float2 f0 = unpack2(s2[i][0]);
            float2 f1 = unpack2(s2[i][1]);
            float2 f2 = unpack2(s2[i][2]);
            float2 f3 = unpack2(s2[i][3]);
            float f[8] = {f0.x, f0.y, f1.x, f1.y, f2.x, f2.y, f3.x, f3.y};
            float mx = f[0];
#pragma unroll
            for (int j = 1; j < 8; j++) mx = fmaxf(mx, f[j]);
#pragma unroll
            for (int off = 8; off >= 1; off >>= 1)
                mx = fmaxf(mx, __shfl_xor_sync(0xffffffffu, mx, off));
            float mnew = fmaxf(m_i[i], mx);
            float corr = __expf(m_i[i] - mnew);
            m_i[i] = mnew;
            float rs = 0.f;
#pragma unroll
            for (int j = 0; j < 8; j++) { f[j] = __expf(f[j] - mnew); rs += f[j]; }
#pragma unroll
            for (int off = 8; off >= 1; off >>= 1)
                rs += __shfl_xor_sync(0xffffffffu, rs, off);
            l_i[i] = l_i[i] * corr + rs;
            ull c2 = pack2(corr);
            mul2(acc_o[i][0], c2);
            mul2(acc_o[i][1], c2);
            *(float4*)&Ps[ty * 8 + i][tx * 8]     = make_float4(f[0], f[1], f[2], f[3]);
            *(float4*)&Ps[ty * 8 + i][tx * 8 + 4] = make_float4(f[4], f[5], f[6], f[7]);
        }
        __syncthreads();

        // ---- O += P @ V (8q x 4d per thread) ----
        for (int k2 = 0; k2 < 128; k2 += 4) {
            float p[8][4];
#pragma unroll
            for (int i = 0; i < 8; i++) {
                float4 t = *(const float4*)&Ps[ty * 8 + i][k2];
                p[i][0] = t.x; p[i][1] = t.y; p[i][2] = t.z; p[i][3] = t.w;
            }
#pragma unroll
            for (int u = 0; u < 4; u++) {
                ulonglong2 vv = *(const ulonglong2*)&Vs[k2 + u][tx * 4];
#pragma unroll
                for (int i = 0; i < 8; i++) {
                    ull pp = pack2(p[i][u]);
                    ffma2(acc_o[i][0], pp, vv.x);
                    ffma2(acc_o[i][1], pp, vv.y);
                }
            }
        }
    }

    // ---- normalize + store to [B,SQ,D] ----
    int b = bh >> 4, h = bh & 15;   // H_ == 16
#pragma unroll
    for (int i = 0; i < 8; i++) {
        float inv = 1.f / l_i[i];
        float2 o0 = unpack2(acc_o[i][0]);
        float2 o1 = unpack2(acc_o[i][1]);
        float4 o = make_float4(o0.x * inv, o0.y * inv, o1.x * inv, o1.y * inv);
        int srow = qbase + ty * 8 + i;
        *(float4*)&Og[((long long)b * SQ_ + srow) * D_ + h * HD_ + tx * 4] = o;
    }
}

// ----------------------------------------------------------------------------
extern "C" void kernel_launch(void* const* d_in, const int* in_sizes, int n_in,
                              void* d_out, int out_size)
{
    const float* x   = (const float*)d_in[0];
    const float* enc = (const float*)d_in[1];
    const float* Wq  = (const float*)d_in[2];
    const float* bq  = (const float*)d_in[3];
    const float* Wk  = (const float*)d_in[4];
    const float* bk  = (const float*)d_in[5];
    const float* Wv  = (const float*)d_in[6];
    const float* bv  = (const float*)d_in[7];
    const float* Wo  = (const float*)d_in[8];
    const float* bo  = (const float*)d_in[9];
    float* out = (float*)d_out;

    float *q, *k, *v, *attn;
    cudaGetSymbolAddress((void**)&q,    g_q);
    cudaGetSymbolAddress((void**)&k,    g_k);
    cudaGetSymbolAddress((void**)&v,    g_v);
    cudaGetSymbolAddress((void**)&attn, g_attn);

    dim3 gq(D_ / 128, (B_ * SQ_) / 128);

    sgemm<1, 1><<<gq, 256>>>(x,   Wq, bq, q, B_ * SQ_, D_, D_, SQ_);
    sgemm<1, 1><<<gq, 256>>>(enc, Wk, bk, k, B_ * SK_, D_, D_, SK_);
    sgemm<1, 1><<<gq, 256>>>(enc, Wv, bv, v, B_ * SK_, D_, D_, SK_);

    int smem = (2 * 64 * 132 + 128 * 68 + 128 * 132) * (int)sizeof(float); // 169984
    cudaFuncSetAttribute(flash2,
                         cudaFuncAttributeMaxDynamicSharedMemorySize, smem);
    flash2<<<dim3(SQ_ / 128, B_ * H_), 256, smem>>>(q, k, v, attn);

    sgemm<0, 0><<<gq, 256>>>(attn, Wo, bo, out, B_ * SQ_, D_, D_, SQ_);
}

// round 7
// speedup vs baseline: 1.3560x; 1.3560x over previous
#include <cuda_runtime.h>
#include <cuda_bf16.h>
#include <cstdint>

#define B_   2
#define SQ_  2048
#define SK_  2048
#define D_   1024
#define H_   16
#define HD_  64

// ---------------------------------------------------------------------------
// Scratch (__device__ globals; allocation-free rule)
// ---------------------------------------------------------------------------
__device__ float g_q[B_*H_*SQ_*HD_];
__device__ float g_k[B_*H_*SK_*HD_];
__device__ float g_v[B_*H_*SK_*HD_];
__device__ float g_attn[B_*SQ_*D_];

__device__ __nv_bfloat16 g_xh[B_*SQ_*D_], g_xl[B_*SQ_*D_];
__device__ __nv_bfloat16 g_eh[B_*SK_*D_], g_el[B_*SK_*D_];
__device__ __nv_bfloat16 g_ah[B_*SQ_*D_], g_al[B_*SQ_*D_];
__device__ __nv_bfloat16 g_wqh[D_*D_], g_wql[D_*D_];   // Bt [N][K]
__device__ __nv_bfloat16 g_wkh[D_*D_], g_wkl[D_*D_];
__device__ __nv_bfloat16 g_wvh[D_*D_], g_wvl[D_*D_];
__device__ __nv_bfloat16 g_woh[D_*D_], g_wol[D_*D_];

// ---------------------------------------------------------------------------
// PTX helpers (compute_103-legal only: cp.async, ldmatrix, mma.sync)
// ---------------------------------------------------------------------------
__device__ __forceinline__ uint32_t smem_u32(const void* p) {
    uint32_t a;
    asm("{ .reg .u64 t; cvta.to.shared.u64 t, %1; cvt.u32.u64 %0, t; }"
        : "=r"(a) : "l"(p));
    return a;
}
__device__ __forceinline__ void cp_async16(uint32_t s, const void* g) {
    asm volatile("cp.async.cg.shared.global [%0], [%1], 16;" :: "r"(s), "l"(g));
}
__device__ __forceinline__ void ldm_x4(uint32_t* r, uint32_t a) {
    asm volatile("ldmatrix.sync.aligned.m8n8.x4.shared.b16 {%0,%1,%2,%3}, [%4];"
        : "=r"(r[0]), "=r"(r[1]), "=r"(r[2]), "=r"(r[3]) : "r"(a));
}
// NON-trans x2: for Bt[n][k] storage this directly yields the .col B fragment
__device__ __forceinline__ void ldm_x2(uint32_t* r, uint32_t a) {
    asm volatile("ldmatrix.sync.aligned.m8n8.x2.shared.b16 {%0,%1}, [%2];"
        : "=r"(r[0]), "=r"(r[1]) : "r"(a));
}
__device__ __forceinline__ void mma16816(float* c, const uint32_t* a, const uint32_t* b) {
    asm volatile("mma.sync.aligned.m16n8k16.row.col.f32.bf16.bf16.f32 "
        "{%0,%1,%2,%3}, {%4,%5,%6,%7}, {%8,%9}, {%0,%1,%2,%3};"
        : "+f"(c[0]), "+f"(c[1]), "+f"(c[2]), "+f"(c[3])
        : "r"(a[0]), "r"(a[1]), "r"(a[2]), "r"(a[3]), "r"(b[0]), "r"(b[1]));
}

// ---------------------------------------------------------------------------
// Conversion kernels
// ---------------------------------------------------------------------------
__global__ void split_elems(const float* __restrict__ x,
                            __nv_bfloat16* __restrict__ hi,
                            __nv_bfloat16* __restrict__ lo, int n)
{
    int i = (blockIdx.x * blockDim.x + threadIdx.x) * 4;
    if (i >= n) return;
    float4 v = *(const float4*)(x + i);
    float vv[4] = {v.x, v.y, v.z, v.w};
    __nv_bfloat16 h[4], l[4];
#pragma unroll
    for (int j = 0; j < 4; j++) {
        h[j] = __float2bfloat16(vv[j]);
        l[j] = __float2bfloat16(vv[j] - __bfloat162float(h[j]));
    }
    *(__nv_bfloat162*)(hi + i)     = __nv_bfloat162(h[0], h[1]);
    *(__nv_bfloat162*)(hi + i + 2) = __nv_bfloat162(h[2], h[3]);
    *(__nv_bfloat162*)(lo + i)     = __nv_bfloat162(l[0], l[1]);
    *(__nv_bfloat162*)(lo + i + 2) = __nv_bfloat162(l[2], l[3]);
}

// out[c][r] = src[r][c] with hi/lo split; z-th matrix of [R][C].
__global__ void transpose_split(const float* __restrict__ src,
                                __nv_bfloat16* __restrict__ hi,
                                __nv_bfloat16* __restrict__ lo, int R, int C)
{
    __shared__ float t[32][33];
    long long zoff = (long long)blockIdx.z * R * C;
    src += zoff; hi += zoff; lo += zoff;
    int c0 = blockIdx.x * 32, r0 = blockIdx.y * 32;
    int tx = threadIdx.x, ty = threadIdx.y;
#pragma unroll
    for (int k = 0; k < 32; k += 8)
        t[ty + k][tx] = src[(long long)(r0 + ty + k) * C + c0 + tx];
    __syncthreads();
#pragma unroll
    for (int k = 0; k < 32; k += 8) {
        float v = t[tx][ty + k];
        __nv_bfloat16 h = __float2bfloat16(v);
        __nv_bfloat16 l = __float2bfloat16(v - __bfloat162float(h));
        hi[(long long)(c0 + ty + k) * R + r0 + tx] = h;
        lo[(long long)(c0 + ty + k) * R + r0 + tx] = l;
    }
}

// ---------------------------------------------------------------------------
// bf16-split GEMM on mma.sync: C[M,N] = A[M,K] @ Bt[N,K]^T + bias[N]
// K=1024. CTA tile 128x128, 8 warps (2m x 4n), warp tile 64x32.
// K-slab 32, cp.async double buffer. 3 terms: AhBh + AhBl + AlBh.
// smem per stage: 4 tiles x 128 rows x 80B = 40960B; 2 stages = 81920B.
// OMODE 0: row-major [M,1024]. OMODE 1: [B,H,S,64].
// ---------------------------------------------------------------------------
#define STG   40960
#define TILEB 10240

template<int OMODE>
__global__ __launch_bounds__(256, 2) void gemm_mma(
    const __nv_bfloat16* __restrict__ Ah, const __nv_bfloat16* __restrict__ Al,
    const __nv_bfloat16* __restrict__ Bh, const __nv_bfloat16* __restrict__ Bl,
    const float* __restrict__ bias, float* __restrict__ C, int S)
{
    extern __shared__ char smem[];
    const int K = 1024;
    uint32_t smb = smem_u32(smem);
    int tid = threadIdx.x;
    int lane = tid & 31, wid = tid >> 5;
    int wm = wid >> 2, wn = wid & 3;
    int row0 = blockIdx.y * 128, col0 = blockIdx.x * 128;

    const __nv_bfloat16* gp[4] = {
        Ah + (long long)row0 * K, Al + (long long)row0 * K,
        Bh + (long long)col0 * K, Bl + (long long)col0 * K };

    float acc[4][4][4];
#pragma unroll
    for (int i = 0; i < 4; i++)
#pragma unroll
        for (int j = 0; j < 4; j++)
#pragma unroll
            for (int u = 0; u < 4; u++) acc[i][j][u] = 0.f;

    // stage loader: 4 tiles x 512 16B-chunks, 8 cp.async per thread
    auto load_stage = [&](int kc, int st) {
        int k0 = kc * 32;
        uint32_t sbase = smb + st * STG;
#pragma unroll
        for (int t = 0; t < 8; t++) {
            const int tile = t >> 1;
            int idx = tid + (t & 1) * 256;       // 0..511
            int r = idx >> 2, c = idx & 3;
            cp_async16(sbase + tile * TILEB + r * 80 + c * 16,
                       gp[tile] + (long long)r * K + k0 + c * 8);
        }
        asm volatile("cp.async.commit_group;" ::: "memory");
    };

    load_stage(0, 0);
    const int NK = K / 32;   // 32

    for (int kc = 0; kc < NK; kc++) {
        if (kc + 1 < NK) {
            load_stage(kc + 1, (kc + 1) & 1);
            asm volatile("cp.async.wait_group 1;" ::: "memory");
        } else {
            asm volatile("cp.async.wait_group 0;" ::: "memory");
        }
        __syncthreads();

        uint32_t sa  = smb + (kc & 1) * STG;
        uint32_t sAh = sa, sAl = sa + TILEB, sBh = sa + 2 * TILEB, sBl = sa + 3 * TILEB;

#pragma unroll
        for (int ks = 0; ks < 2; ks++) {
            uint32_t ah[4][4], al[4][4], bh[4][2], bl[4][2];
            uint32_t aoff = (uint32_t)(wm * 64 + (lane & 15)) * 80
                          + ks * 32 + (lane >> 4) * 16;
#pragma unroll
            for (int i = 0; i < 4; i++) {
                ldm_x4(ah[i], sAh + aoff + i * 16 * 80);
                ldm_x4(al[i], sAl + aoff + i * 16 * 80);
            }
            // B: lanes 0-7 -> n rows (k 0-7), lanes 8-15 -> same n rows (k 8-15)
            uint32_t boff = (uint32_t)(wn * 32 + (lane & 7)) * 80
                          + ks * 32 + ((lane >> 3) & 1) * 16;
#pragma unroll
            for (int j = 0; j < 4; j++) {
                ldm_x2(bh[j], sBh + boff + j * 8 * 80);
                ldm_x2(bl[j], sBl + boff + j * 8 * 80);
            }
#pragma unroll
            for (int i = 0; i < 4; i++)
#pragma unroll
                for (int j = 0; j < 4; j++) {
                    mma16816(acc[i][j], ah[i], bh[j]);
                    mma16816(acc[i][j], ah[i], bl[j]);
                    mma16816(acc[i][j], al[i], bh[j]);
                }
        }
        __syncthreads();
    }

    // Epilogue: bias + store. c0/c1 -> (r, c..c+1); c2/c3 -> (r+8, c..c+1)
#pragma unroll
    for (int i = 0; i < 4; i++) {
        int r = row0 + wm * 64 + i * 16 + (lane >> 2);
#pragma unroll
        for (int j = 0; j < 4; j++) {
            int c = col0 + wn * 32 + j * 8 + (lane & 3) * 2;
            float bx = bias[c], by = bias[c + 1];
            float2 v0 = make_float2(acc[i][j][0] + bx, acc[i][j][1] + by);
            float2 v1 = make_float2(acc[i][j][2] + bx, acc[i][j][3] + by);
            long long i0, i1;
            if (OMODE == 0) {
                i0 = (long long)r * 1024 + c;
                i1 = i0 + 8 * 1024;
            } else {
                int b = r / S, s = r - b * S;
                int h = c >> 6, e = c & 63;
                i0 = (((long long)(b * H_ + h) * S) + s) * HD_ + e;
                i1 = i0 + 8 * HD_;     // s+8, same (b,h)
            }
            *(float2*)&C[i0] = v0;
            *(float2*)&C[i1] = v1;
        }
    }
}

// ---------------------------------------------------------------------------
// Flash attention (fp32, proven R2 kernel): block = 64 q rows of one (b,h).
// ---------------------------------------------------------------------------
__global__ __launch_bounds__(256) void flash_attn(
    const float* __restrict__ Q, const float* __restrict__ Kg,
    const float* __restrict__ Vg, float* __restrict__ Og)
{
    extern __shared__ float sm[];
    float (*Qs)[68]  = (float(*)[68])(sm);
    float (*Kst)[68] = (float(*)[68])(sm + 64 * 68);
    float (*Vs)[68]  = (float(*)[68])(sm + 2 * 64 * 68);
    float (*Ps)[68]  = (float(*)[68])(sm + 3 * 64 * 68);

    int tid = threadIdx.x;
    int tx = tid & 15, ty = tid >> 4;
    int bh = blockIdx.y;
    int qbase = blockIdx.x * 64;

    const float* Qp = Q + ((long long)bh * SQ_ + qbase) * HD_;
    const float* Kp = Kg + (long long)bh * SK_ * HD_;
    const float* Vp = Vg + (long long)bh * SK_ * HD_;

    for (int i = tid; i < 64 * 64; i += 256) {
        int r = i >> 6, d = i & 63;
        Qs[r][d] = Qp[(long long)r * HD_ + d] * 0.125f;
    }

    float m_i[4], l_i[4], acc[4][4];
#pragma unroll
    for (int i = 0; i < 4; i++) {
        m_i[i] = -1e30f; l_i[i] = 0.f;
#pragma unroll
        for (int j = 0; j < 4; j++) acc[i][j] = 0.f;
    }

    for (int kt = 0; kt < SK_; kt += 64) {
        __syncthreads();
        for (int i = tid; i < 64 * 64; i += 256) {
            int r = i >> 6, d = i & 63;
            Kst[d][r] = Kp[(long long)(kt + r) * HD_ + d];
            Vs[r][d]  = Vp[(long long)(kt + r) * HD_ + d];
        }
        __syncthreads();

        float s[4][4];
#pragma unroll
        for (int i = 0; i < 4; i++)
#pragma unroll
            for (int j = 0; j < 4; j++) s[i][j] = 0.f;

#pragma unroll 8
        for (int d = 0; d < 64; d++) {
            float4 kv = *(const float4*)&Kst[d][tx * 4];
#pragma unroll
            for (int i = 0; i < 4; i++) {
                float qv = Qs[ty * 4 + i][d];
                s[i][0] += qv * kv.x;
                s[i][1] += qv * kv.y;
                s[i][2] += qv * kv.z;
                s[i][3] += qv * kv.w;
            }
        }

#pragma unroll
        for (int i = 0; i < 4; i++) {
            float mx = fmaxf(fmaxf(s[i][0], s[i][1]), fmaxf(s[i][2], s[i][3]));
#pragma unroll
            for (int off = 8; off >= 1; off >>= 1)
                mx = fmaxf(mx, __shfl_xor_sync(0xffffffffu, mx, off));
            float mnew = fmaxf(m_i[i], mx);
            float corr = __expf(m_i[i] - mnew);
            m_i[i] = mnew;
            float rs = 0.f;
#pragma unroll
            for (int j = 0; j < 4; j++) {
                s[i][j] = __expf(s[i][j] - mnew);
                rs += s[i][j];
            }
#pragma unroll
            for (int off = 8; off >= 1; off >>= 1)
                rs += __shfl_xor_sync(0xffffffffu, rs, off);
            l_i[i] = l_i[i] * corr + rs;
#pragma unroll
            for (int j = 0; j < 4; j++) acc[i][j] *= corr;
            *(float4*)&Ps[ty * 4 + i][tx * 4] =
                make_float4(s[i][0], s[i][1], s[i][2], s[i][3]);
        }
        __syncthreads();

#pragma unroll 8
        for (int k2 = 0; k2 < 64; k2++) {
            float4 vv = *(const float4*)&Vs[k2][tx * 4];
#pragma unroll
            for (int i = 0; i < 4; i++) {
                float pv = Ps[ty * 4 + i][k2];
                acc[i][0] += pv * vv.x;
                acc[i][1] += pv * vv.y;
                acc[i][2] += pv * vv.z;
                acc[i][3] += pv * vv.w;
            }
        }
    }

    int b = bh >> 4, h = bh & 15;
#pragma unroll
    for (int i = 0; i < 4; i++) {
        float inv = 1.f / l_i[i];
        int srow = qbase + ty * 4 + i;
        float4 o = make_float4(acc[i][0] * inv, acc[i][1] * inv,
                               acc[i][2] * inv, acc[i][3] * inv);
        *(float4*)&Og[((long long)b * SQ_ + srow) * D_ + h * HD_ + tx * 4] = o;
    }
}

// ---------------------------------------------------------------------------
extern "C" void kernel_launch(void* const* d_in, const int* in_sizes, int n_in,
                              void* d_out, int out_size)
{
    const float* x   = (const float*)d_in[0];
    const float* enc = (const float*)d_in[1];
    const float* Wq  = (const float*)d_in[2];
    const float* bq  = (const float*)d_in[3];
    const float* Wk  = (const float*)d_in[4];
    const float* bk  = (const float*)d_in[5];
    const float* Wv  = (const float*)d_in[6];
    const float* bv  = (const float*)d_in[7];
    const float* Wo  = (const float*)d_in[8];
    const float* bo  = (const float*)d_in[9];
    float* out = (float*)d_out;

    float *q, *k, *v, *attn;
    cudaGetSymbolAddress((void**)&q,    g_q);
    cudaGetSymbolAddress((void**)&k,    g_k);
    cudaGetSymbolAddress((void**)&v,    g_v);
    cudaGetSymbolAddress((void**)&attn, g_attn);

    __nv_bfloat16 *xh,*xl,*eh,*el,*ah,*al;
    __nv_bfloat16 *wqh,*wql,*wkh,*wkl,*wvh,*wvl,*woh,*wol;
    cudaGetSymbolAddress((void**)&xh, g_xh);  cudaGetSymbolAddress((void**)&xl, g_xl);
    cudaGetSymbolAddress((void**)&eh, g_eh);  cudaGetSymbolAddress((void**)&el, g_el);
    cudaGetSymbolAddress((void**)&ah, g_ah);  cudaGetSymbolAddress((void**)&al, g_al);
    cudaGetSymbolAddress((void**)&wqh, g_wqh); cudaGetSymbolAddress((void**)&wql, g_wql);
    cudaGetSymbolAddress((void**)&wkh, g_wkh); cudaGetSymbolAddress((void**)&wkl, g_wkl);
    cudaGetSymbolAddress((void**)&wvh, g_wvh); cudaGetSymbolAddress((void**)&wvl, g_wvl);
    cudaGetSymbolAddress((void**)&woh, g_woh); cudaGetSymbolAddress((void**)&wol, g_wol);

    const int NACT = B_ * SQ_ * D_;   // 4M

    // 1. Split activations to bf16 hi/lo
    split_elems<<<NACT / 4 / 256, 256>>>(x,   xh, xl, NACT);
    split_elems<<<NACT / 4 / 256, 256>>>(enc, eh, el, NACT);

    // 2. Transpose+split weights -> Bt [N][K]
    dim3 tt(32, 8);
    transpose_split<<<dim3(2, 32, 16), tt>>>(Wq, wqh, wql, 1024, 64);
    transpose_split<<<dim3(2, 32, 16), tt>>>(Wk, wkh, wkl, 1024, 64);
    transpose_split<<<dim3(2, 32, 16), tt>>>(Wv, wvh, wvl, 1024, 64);
    transpose_split<<<dim3(32, 32, 1), tt>>>(Wo, woh, wol, 1024, 1024);

    // 3. QKV projections on HMMA -> [B,H,S,64]
    dim3 gg(1024 / 128, 4096 / 128);   // 8 x 32
    int gsm = 2 * STG;                 // 81920
    cudaFuncSetAttribute(gemm_mma<0>, cudaFuncAttributeMaxDynamicSharedMemorySize, gsm);
    cudaFuncSetAttribute(gemm_mma<1>, cudaFuncAttributeMaxDynamicSharedMemorySize, gsm);
    gemm_mma<1><<<gg, 256, gsm>>>(xh, xl, wqh, wql, bq, q, SQ_);
    gemm_mma<1><<<gg, 256, gsm>>>(eh, el, wkh, wkl, bk, k, SK_);
    gemm_mma<1><<<gg, 256, gsm>>>(eh, el, wvh, wvl, bv, v, SK_);

    // 4. Flash attention (fp32) -> [B,SQ,D]
    int fsm = 4 * 64 * 68 * (int)sizeof(float);
    cudaFuncSetAttribute(flash_attn, cudaFuncAttributeMaxDynamicSharedMemorySize, fsm);
    flash_attn<<<dim3(SQ_ / 64, B_ * H_), 256, fsm>>>(q, k, v, attn);

    // 5. Split attention output, final projection -> d_out
    split_elems<<<NACT / 4 / 256, 256>>>(attn, ah, al, NACT);
    gemm_mma<0><<<gg, 256, gsm>>>(ah, al, woh, wol, bo, out, SQ_);
}